// round 13
// baseline (speedup 1.0000x reference)
#include <cuda_runtime.h>
#include <cuda_fp16.h>
#include <cstdint>

#define TOK 8192      // B*S
#define DD  1024      // model dim
#define FF  4096      // ffn dim
#define NE  8         // experts
// top-k = 2

// ---------------- PTX helpers ----------------
__device__ __forceinline__ uint32_t smem_u32(const void* p) {
    uint32_t a;
    asm("{ .reg .u64 t; cvta.to.shared.u64 t, %1; cvt.u32.u64 %0, t; }" : "=r"(a) : "l"(p));
    return a;
}
__device__ __forceinline__ void cp16(uint32_t dst, const void* src) {
    asm volatile("cp.async.cg.shared.global [%0], [%1], 16;" :: "r"(dst), "l"(src));
}
// L1-caching variant: use for A tiles (co-resident CTAs share identical A rows)
__device__ __forceinline__ void cp16ca(uint32_t dst, const void* src) {
    asm volatile("cp.async.ca.shared.global [%0], [%1], 16;" :: "r"(dst), "l"(src));
}
__device__ __forceinline__ void cp16cap(uint32_t dst, const void* src, bool pred) {
    int sz = pred ? 16 : 0;   // sz=0 -> zero-fill 16B
    asm volatile("cp.async.ca.shared.global [%0], [%1], 16, %2;" :: "r"(dst), "l"(src), "r"(sz));
}
#define CP_COMMIT() asm volatile("cp.async.commit_group;" ::: "memory")
#define CP_WAIT(n)  asm volatile("cp.async.wait_group %0;" :: "n"(n) : "memory")

__device__ __forceinline__ void ldsm4(uint32_t& r0, uint32_t& r1, uint32_t& r2, uint32_t& r3, uint32_t a) {
    asm volatile("ldmatrix.sync.aligned.m8n8.x4.shared.b16 {%0,%1,%2,%3}, [%4];"
        : "=r"(r0), "=r"(r1), "=r"(r2), "=r"(r3) : "r"(a));
}
__device__ __forceinline__ void ldsm4t(uint32_t& r0, uint32_t& r1, uint32_t& r2, uint32_t& r3, uint32_t a) {
    asm volatile("ldmatrix.sync.aligned.m8n8.x4.trans.shared.b16 {%0,%1,%2,%3}, [%4];"
        : "=r"(r0), "=r"(r1), "=r"(r2), "=r"(r3) : "r"(a));
}
__device__ __forceinline__ void mma16816(float* d, uint32_t a0, uint32_t a1, uint32_t a2, uint32_t a3,
                                         uint32_t b0, uint32_t b1) {
    asm volatile("mma.sync.aligned.m16n8k16.row.col.f32.f16.f16.f32 "
        "{%0,%1,%2,%3}, {%4,%5,%6,%7}, {%8,%9}, {%0,%1,%2,%3};"
        : "+f"(d[0]), "+f"(d[1]), "+f"(d[2]), "+f"(d[3])
        : "r"(a0), "r"(a1), "r"(a2), "r"(a3), "r"(b0), "r"(b1));
}
#define SWZ(x) ((uint32_t)(x) ^ ((((uint32_t)(x)) >> 3) & 0x70))

// ---------------- device scratch ----------------
__device__ __half g_Xh  [(size_t)TOK * DD];
__device__ __half g_W1ah[(size_t)NE * DD * FF];      // [E][D][F]
__device__ __half g_W1bh[(size_t)NE * DD * FF];
__device__ __half g_W2h [(size_t)NE * FF * DD];      // [E][F][D]
__device__ __half g_H   [(size_t)2 * TOK * FF];
__device__ __half g_Yh  [(size_t)2 * TOK * DD];      // expert output, fp16
__device__ int    g_cnt [NE];
__device__ int    g_off [NE];
__device__ int    g_tlist[NE * TOK];
__device__ int    g_loc [2 * TOK];
__device__ int    g_exp [2 * TOK];
__device__ float  g_gw  [2 * TOK];

// ---------------- small kernels ----------------
__global__ void k_init_cnt() { if (threadIdx.x < NE) g_cnt[threadIdx.x] = 0; }

// W1a/W1b conversion, 2 float4 per thread (blockIdx.y: 0=W1a, 1=W1b)
__global__ void k_cvt_ab(const float* __restrict__ a, const float* __restrict__ b) {
    const float* src = blockIdx.y ? b : a;
    __half* dst = blockIdx.y ? g_W1bh : g_W1ah;
    size_t i = 2 * ((size_t)blockIdx.x * blockDim.x + threadIdx.x);
    float4 v0 = ((const float4*)src)[i];
    float4 v1 = ((const float4*)src)[i + 1];
    __half2* d2 = (__half2*)dst;
    d2[2 * i]     = __floats2half2_rn(v0.x, v0.y);
    d2[2 * i + 1] = __floats2half2_rn(v0.z, v0.w);
    d2[2 * i + 2] = __floats2half2_rn(v1.x, v1.y);
    d2[2 * i + 3] = __floats2half2_rn(v1.z, v1.w);
}

// W2 conversion, 2 float4 per thread
__global__ void k_cvt_w2(const float* __restrict__ src) {
    size_t i = 2 * ((size_t)blockIdx.x * blockDim.x + threadIdx.x);
    float4 v0 = ((const float4*)src)[i];
    float4 v1 = ((const float4*)src)[i + 1];
    __half2* d2 = (__half2*)g_W2h;
    d2[2 * i]     = __floats2half2_rn(v0.x, v0.y);
    d2[2 * i + 1] = __floats2half2_rn(v0.z, v0.w);
    d2[2 * i + 2] = __floats2half2_rn(v1.x, v1.y);
    d2[2 * i + 3] = __floats2half2_rn(v1.z, v1.w);
}

// RMSNorm + gating (coalesced) + top-2 + scatter. One block per token, 256 threads.
__global__ void k_rms_gate(const float* __restrict__ x,
                           const float* __restrict__ lnw,
                           const float* __restrict__ Wg,
                           const float* __restrict__ bg) {
    int t = blockIdx.x;
    int tid = threadIdx.x, warp = tid >> 5, lane = tid & 31;

    __shared__ float red[8];
    __shared__ float sscale;
    __shared__ __align__(16) float sxn[DD];
    __shared__ float pe[8][8];

    float4 v = ((const float4*)(x + (size_t)t * DD))[tid];
    float ss = v.x * v.x + v.y * v.y + v.z * v.z + v.w * v.w;
#pragma unroll
    for (int o = 16; o; o >>= 1) ss += __shfl_xor_sync(0xffffffffu, ss, o);
    if (lane == 0) red[warp] = ss;
    __syncthreads();
    if (tid == 0) {
        float tot = 0.f;
#pragma unroll
        for (int w = 0; w < 8; w++) tot += red[w];
        sscale = rsqrtf(tot * (1.0f / (float)DD) + 1.1920928955078125e-7f);
    }
    __syncthreads();
    float s = sscale;

    float4 lw = ((const float4*)lnw)[tid];
    float4 xn;
    xn.x = v.x * s * lw.x; xn.y = v.y * s * lw.y;
    xn.z = v.z * s * lw.z; xn.w = v.w * s * lw.w;

    __half2* xh = (__half2*)(g_Xh + (size_t)t * DD);
    xh[2 * tid]     = __floats2half2_rn(xn.x, xn.y);
    xh[2 * tid + 1] = __floats2half2_rn(xn.z, xn.w);

    ((float4*)sxn)[tid] = xn;
    __syncthreads();

    {
        int dbase = tid >> 3;
        float acc = 0.f;
#pragma unroll
        for (int i = 0; i < 32; i++)
            acc += __ldg(&Wg[tid + 256 * i]) * sxn[dbase + 32 * i];
        acc += __shfl_xor_sync(0xffffffffu, acc, 8);
        acc += __shfl_xor_sync(0xffffffffu, acc, 16);
        if (lane < 8) pe[warp][lane] = acc;
    }
    __syncthreads();

    if (tid == 0) {
        float lg[8];
#pragma unroll
        for (int e = 0; e < 8; e++) {
            float acc = bg[e];
#pragma unroll
            for (int w = 0; w < 8; w++) acc += pe[w][e];
            lg[e] = acc;
        }
        int i1 = 0;
#pragma unroll
        for (int e = 1; e < 8; e++) if (lg[e] > lg[i1]) i1 = e;
        int i2 = -1;
#pragma unroll
        for (int e = 0; e < 8; e++) {
            if (e == i1) continue;
            if (i2 < 0 || lg[e] > lg[i2]) i2 = e;
        }
        float z  = expf(lg[i2] - lg[i1]);
        float w1 = 1.0f / (1.0f + z);
        float w2 = 1.0f - w1;

        int p1 = atomicAdd(&g_cnt[i1], 1);
        g_tlist[i1 * TOK + p1] = t;
        g_loc[2 * t] = p1; g_exp[2 * t] = i1; g_gw[2 * t] = w1;

        int p2 = atomicAdd(&g_cnt[i2], 1);
        g_tlist[i2 * TOK + p2] = t;
        g_loc[2 * t + 1] = p2; g_exp[2 * t + 1] = i2; g_gw[2 * t + 1] = w2;
    }
}

__global__ void k_prefix() {
    int acc = 0;
#pragma unroll
    for (int e = 0; e < NE; e++) { g_off[e] = acc; acc += g_cnt[e]; }
}

// ================= GEMM 1: H = silu(X@W1a+b1a)*(X@W1b+b1b) =================
// CTA 128x64 (both weights), BK=64, 3-stage cp.async. stage 32KB; x3 = 96KB; occ 2.
#define G1_STAGE 32768
#define G1_SMEM  (G1_STAGE * 3)
__global__ __launch_bounds__(256, 2)
void k_gemm1(const float* __restrict__ b1a, const float* __restrict__ b1b) {
    extern __shared__ __align__(16) char smem[];
    int e   = blockIdx.z;
    int cnt = g_cnt[e];
    int m0  = blockIdx.y * 128;
    if (m0 >= cnt) return;
    int n0  = blockIdx.x * 64;

    uint32_t sb = smem_u32(smem);
    int tid = threadIdx.x, warp = tid >> 5, lane = tid & 31;
    int wm = warp >> 1, wn = warp & 1;   // 4x2 warp grid; warp tile 32 x 32 (per matrix)

    int lrow = tid >> 3;
    int lc   = tid & 7;
    int tok[4];
    bool ap[4];
#pragma unroll
    for (int i = 0; i < 4; i++) {
        int r = lrow + 32 * i;
        ap[i]  = (m0 + r < cnt);
        tok[i] = ap[i] ? g_tlist[e * TOK + m0 + r] : 0;
    }
    const __half* Wa = g_W1ah + (size_t)e * DD * FF + n0 + lc * 8;
    const __half* Wb = g_W1bh + (size_t)e * DD * FF + n0 + lc * 8;

    float accA[2][4][4], accB[2][4][4];
#pragma unroll
    for (int i = 0; i < 2; i++)
#pragma unroll
        for (int j = 0; j < 4; j++)
#pragma unroll
            for (int q = 0; q < 4; q++) { accA[i][j][q] = 0.f; accB[i][j][q] = 0.f; }

    auto load_stage = [&](int s, int k0) {
        uint32_t base = sb + s * G1_STAGE;
#pragma unroll
        for (int i = 0; i < 4; i++) {
            int r = lrow + 32 * i;
            cp16cap(base + SWZ(r * 128 + lc * 16), g_Xh + (size_t)tok[i] * DD + k0 + lc * 8, ap[i]);
        }
#pragma unroll
        for (int i = 0; i < 2; i++) {
            int r = lrow + 32 * i;
            uint32_t o = SWZ(r * 128 + lc * 16);
            cp16(base + 16384 + o, Wa + (size_t)(k0 + r) * FF);
            cp16(base + 24576 + o, Wb + (size_t)(k0 + r) * FF);
        }
    };

    const int ITERS = DD / 64;   // 16
    load_stage(0, 0);  CP_COMMIT();
    load_stage(1, 64); CP_COMMIT();

    int l16 = lane & 15, lh = lane >> 4;
    for (int it = 0; it < ITERS; ++it) {
        CP_WAIT(1);
        __syncthreads();
        if (it + 2 < ITERS) load_stage((it + 2) % 3, (it + 2) * 64);
        CP_COMMIT();

        uint32_t Ab  = sb + (it % 3) * G1_STAGE;
        uint32_t Bab = Ab + 16384;
        uint32_t Bbb = Ab + 24576;
#pragma unroll
        for (int kk = 0; kk < 4; kk++) {
            uint32_t a[2][4];
#pragma unroll
            for (int i = 0; i < 2; i++)
                ldsm4(a[i][0], a[i][1], a[i][2], a[i][3],
                      Ab + SWZ((wm * 32 + i * 16 + l16) * 128 + kk * 32 + lh * 16));
#pragma unroll
            for (int jb = 0; jb < 2; jb++) {
                uint32_t boff = SWZ((kk * 16 + l16) * 128 + wn * 64 + jb * 32 + lh * 16);
                uint32_t b0, b1, b2, b3;
                ldsm4t(b0, b1, b2, b3, Bab + boff);
#pragma unroll
                for (int i = 0; i < 2; i++) {
                    mma16816(accA[i][jb * 2],     a[i][0], a[i][1], a[i][2], a[i][3], b0, b1);
                    mma16816(accA[i][jb * 2 + 1], a[i][0], a[i][1], a[i][2], a[i][3], b2, b3);
                }
                ldsm4t(b0, b1, b2, b3, Bbb + boff);
#pragma unroll
                for (int i = 0; i < 2; i++) {
                    mma16816(accB[i][jb * 2],     a[i][0], a[i][1], a[i][2], a[i][3], b0, b1);
                    mma16816(accB[i][jb * 2 + 1], a[i][0], a[i][1], a[i][2], a[i][3], b2, b3);
                }
            }
        }
    }

    int off_e = g_off[e];
    int r_lo = lane >> 2, cp2 = (lane & 3) * 2;
#pragma unroll
    for (int i = 0; i < 2; i++) {
#pragma unroll
        for (int rr = 0; rr < 2; rr++) {
            int m = m0 + wm * 32 + i * 16 + rr * 8 + r_lo;
            if (m >= cnt) continue;
            __half* Hrow = g_H + (size_t)(off_e + m) * FF;
#pragma unroll
            for (int j = 0; j < 4; j++) {
                int nc = n0 + wn * 32 + j * 8 + cp2;
                float a0 = accA[i][j][rr * 2]     + __ldg(&b1a[(size_t)e * FF + nc]);
                float a1 = accA[i][j][rr * 2 + 1] + __ldg(&b1a[(size_t)e * FF + nc + 1]);
                float v0 = accB[i][j][rr * 2]     + __ldg(&b1b[(size_t)e * FF + nc]);
                float v1 = accB[i][j][rr * 2 + 1] + __ldg(&b1b[(size_t)e * FF + nc + 1]);
                float h0 = a0 / (1.0f + __expf(-a0)) * v0;
                float h1 = a1 / (1.0f + __expf(-a1)) * v1;
                *(__half2*)(Hrow + nc) = __floats2half2_rn(h0, h1);
            }
        }
    }
}

// ================= GEMM 2: Y = H @ W2 + b2 (fp16 Y) =================
// CTA 128x128, BK=64, B as two 64-col panels. stage 32KB; x3 = 96KB; occ 2.
#define G2_STAGE 32768
#define G2_SMEM  (G2_STAGE * 3)
__global__ __launch_bounds__(256, 2)
void k_gemm2(const float* __restrict__ b2) {
    extern __shared__ __align__(16) char smem[];
    int e   = blockIdx.z;
    int cnt = g_cnt[e];
    int m0  = blockIdx.y * 128;
    if (m0 >= cnt) return;
    int n0  = blockIdx.x * 128;

    uint32_t sb = smem_u32(smem);
    int tid = threadIdx.x, warp = tid >> 5, lane = tid & 31;
    int wm = warp >> 1, wn = warp & 1;

    int off_e = g_off[e];
    int lrow = tid >> 3;
    int lc   = tid & 7;
    bool ap[4];
    const __half* Arow[4];
#pragma unroll
    for (int i = 0; i < 4; i++) {
        int r = lrow + 32 * i;
        ap[i]   = (m0 + r < cnt);
        Arow[i] = g_H + (size_t)(off_e + (ap[i] ? m0 + r : 0)) * FF;
    }
    const __half* WB = g_W2h + (size_t)e * FF * DD + n0 + lc * 8;

    float acc[2][8][4];
#pragma unroll
    for (int i = 0; i < 2; i++)
#pragma unroll
        for (int j = 0; j < 8; j++)
#pragma unroll
            for (int q = 0; q < 4; q++) acc[i][j][q] = 0.f;

    auto load_stage = [&](int s, int k0) {
        uint32_t base = sb + s * G2_STAGE;
#pragma unroll
        for (int i = 0; i < 4; i++) {
            int r = lrow + 32 * i;
            cp16cap(base + SWZ(r * 128 + lc * 16), Arow[i] + k0 + lc * 8, ap[i]);
        }
#pragma unroll
        for (int p = 0; p < 2; p++)
#pragma unroll
            for (int i = 0; i < 2; i++) {
                int r = lrow + 32 * i;
                cp16(base + 16384 + p * 8192 + SWZ(r * 128 + lc * 16),
                     WB + (size_t)(k0 + r) * DD + p * 64);
            }
    };

    const int ITERS = FF / 64;   // 64
    load_stage(0, 0);  CP_COMMIT();
    load_stage(1, 64); CP_COMMIT();

    int l16 = lane & 15, lh = lane >> 4;
    for (int it = 0; it < ITERS; ++it) {
        CP_WAIT(1);
        __syncthreads();
        if (it + 2 < ITERS) load_stage((it + 2) % 3, (it + 2) * 64);
        CP_COMMIT();

        uint32_t Ab = sb + (it % 3) * G2_STAGE;
        uint32_t Bb = Ab + 16384 + wn * 8192;   // this warp's 64-col panel
#pragma unroll
        for (int kk = 0; kk < 4; kk++) {
            uint32_t a[2][4];
#pragma unroll
            for (int i = 0; i < 2; i++)
                ldsm4(a[i][0], a[i][1], a[i][2], a[i][3],
                      Ab + SWZ((wm * 32 + i * 16 + l16) * 128 + kk * 32 + lh * 16));
#pragma unroll
            for (int jb = 0; jb < 4; jb++) {
                uint32_t b0, b1, b2, b3;
                ldsm4t(b0, b1, b2, b3, Bb + SWZ((kk * 16 + l16) * 128 + jb * 32 + lh * 16));
#pragma unroll
                for (int i = 0; i < 2; i++) {
                    mma16816(acc[i][jb * 2],     a[i][0], a[i][1], a[i][2], a[i][3], b0, b1);
                    mma16816(acc[i][jb * 2 + 1], a[i][0], a[i][1], a[i][2], a[i][3], b2, b3);
                }
            }
        }
    }

    int r_lo = lane >> 2, cp2 = (lane & 3) * 2;
#pragma unroll
    for (int i = 0; i < 2; i++) {
#pragma unroll
        for (int rr = 0; rr < 2; rr++) {
            int m = m0 + wm * 32 + i * 16 + rr * 8 + r_lo;
            if (m >= cnt) continue;
            __half* Yrow = g_Yh + (size_t)(off_e + m) * DD;
#pragma unroll
            for (int j = 0; j < 8; j++) {
                int nc = n0 + wn * 64 + j * 8 + cp2;
                float y0 = acc[i][j][rr * 2]     + __ldg(&b2[(size_t)e * DD + nc]);
                float y1 = acc[i][j][rr * 2 + 1] + __ldg(&b2[(size_t)e * DD + nc + 1]);
                *(__half2*)(Yrow + nc) = __floats2half2_rn(y0, y1);
            }
        }
    }
}

// ---------------- combine (fp16 Y inputs) ----------------
__global__ void k_combine(float* __restrict__ out) {
    int t = blockIdx.x;
    int e0 = g_exp[2 * t], e1 = g_exp[2 * t + 1];
    size_t r0 = (size_t)(g_off[e0] + g_loc[2 * t]);
    size_t r1 = (size_t)(g_off[e1] + g_loc[2 * t + 1]);
    float w0 = g_gw[2 * t], w1 = g_gw[2 * t + 1];

    // 256 threads, 4 halves each (one uint2 = 4 fp16)
    const uint2* y0 = (const uint2*)(g_Yh + r0 * DD);
    const uint2* y1 = (const uint2*)(g_Yh + r1 * DD);
    uint2 pa = y0[threadIdx.x];
    uint2 pb = y1[threadIdx.x];
    __half2 a01 = *(__half2*)&pa.x, a23 = *(__half2*)&pa.y;
    __half2 b01 = *(__half2*)&pb.x, b23 = *(__half2*)&pb.y;
    float2 fa01 = __half22float2(a01), fa23 = __half22float2(a23);
    float2 fb01 = __half22float2(b01), fb23 = __half22float2(b23);
    float4 o;
    o.x = w0 * fa01.x + w1 * fb01.x;
    o.y = w0 * fa01.y + w1 * fb01.y;
    o.z = w0 * fa23.x + w1 * fb23.x;
    o.w = w0 * fa23.y + w1 * fb23.y;
    ((float4*)(out + (size_t)t * DD))[threadIdx.x] = o;
}

// ---------------- launch ----------------
extern "C" void kernel_launch(void* const* d_in, const int* in_sizes, int n_in,
                              void* d_out, int out_size) {
    const float* x   = (const float*)d_in[0];
    const float* lnw = (const float*)d_in[1];
    const float* Wg  = (const float*)d_in[2];
    const float* bg  = (const float*)d_in[3];
    const float* W1a = (const float*)d_in[4];
    const float* b1a = (const float*)d_in[5];
    const float* W1b = (const float*)d_in[6];
    const float* b1b = (const float*)d_in[7];
    const float* W2  = (const float*)d_in[8];
    const float* b2  = (const float*)d_in[9];
    float* out = (float*)d_out;

    static int inited = 0;
    static cudaStream_t s1;
    static cudaEvent_t evFork, evAb, evW2;
    if (!inited) {
        cudaFuncSetAttribute(k_gemm1, cudaFuncAttributeMaxDynamicSharedMemorySize, G1_SMEM);
        cudaFuncSetAttribute(k_gemm2, cudaFuncAttributeMaxDynamicSharedMemorySize, G2_SMEM);
        cudaStreamCreateWithFlags(&s1, cudaStreamNonBlocking);
        cudaEventCreateWithFlags(&evFork, cudaEventDisableTiming);
        cudaEventCreateWithFlags(&evAb, cudaEventDisableTiming);
        cudaEventCreateWithFlags(&evW2, cudaEventDisableTiming);
        inited = 1;
    }

    k_init_cnt<<<1, 32>>>();

    // fork conversion stream off the capture (default) stream
    cudaEventRecord(evFork, 0);
    cudaStreamWaitEvent(s1, evFork, 0);

    const int n8 = NE * DD * FF / 8;   // 2-float4 units per weight tensor
    k_cvt_ab<<<dim3(n8 / 256, 2), 256, 0, s1>>>(W1a, W1b);
    cudaEventRecord(evAb, s1);
    k_cvt_w2<<<n8 / 256, 256, 0, s1>>>(W2);
    cudaEventRecord(evW2, s1);

    // routing on the main stream, concurrent with conversions
    k_rms_gate<<<TOK, 256>>>(x, lnw, Wg, bg);
    k_prefix<<<1, 1>>>();

    cudaStreamWaitEvent(0, evAb, 0);
    k_gemm1<<<dim3(FF / 64, TOK / 128, NE), 256, G1_SMEM>>>(b1a, b1b);

    cudaStreamWaitEvent(0, evW2, 0);
    k_gemm2<<<dim3(DD / 128, TOK / 128, NE), 256, G2_SMEM>>>(b2);

    k_combine<<<TOK, 256>>>(out);
}

// round 15
// speedup vs baseline: 1.0993x; 1.0993x over previous
#include <cuda_runtime.h>
#include <cuda_fp16.h>
#include <cstdint>

#define TOK 8192      // B*S
#define DD  1024      // model dim
#define FF  4096      // ffn dim
#define NE  8         // experts
// top-k = 2

// ---------------- PTX helpers ----------------
__device__ __forceinline__ uint32_t smem_u32(const void* p) {
    uint32_t a;
    asm("{ .reg .u64 t; cvta.to.shared.u64 t, %1; cvt.u32.u64 %0, t; }" : "=r"(a) : "l"(p));
    return a;
}
__device__ __forceinline__ void cp16(uint32_t dst, const void* src) {
    asm volatile("cp.async.cg.shared.global [%0], [%1], 16;" :: "r"(dst), "l"(src));
}
__device__ __forceinline__ void cp16p(uint32_t dst, const void* src, bool pred) {
    int sz = pred ? 16 : 0;   // sz=0 -> zero-fill 16B
    asm volatile("cp.async.cg.shared.global [%0], [%1], 16, %2;" :: "r"(dst), "l"(src), "r"(sz));
}
#define CP_COMMIT() asm volatile("cp.async.commit_group;" ::: "memory")
#define CP_WAIT(n)  asm volatile("cp.async.wait_group %0;" :: "n"(n) : "memory")

__device__ __forceinline__ void ldsm4(uint32_t& r0, uint32_t& r1, uint32_t& r2, uint32_t& r3, uint32_t a) {
    asm volatile("ldmatrix.sync.aligned.m8n8.x4.shared.b16 {%0,%1,%2,%3}, [%4];"
        : "=r"(r0), "=r"(r1), "=r"(r2), "=r"(r3) : "r"(a));
}
__device__ __forceinline__ void ldsm4t(uint32_t& r0, uint32_t& r1, uint32_t& r2, uint32_t& r3, uint32_t a) {
    asm volatile("ldmatrix.sync.aligned.m8n8.x4.trans.shared.b16 {%0,%1,%2,%3}, [%4];"
        : "=r"(r0), "=r"(r1), "=r"(r2), "=r"(r3) : "r"(a));
}
__device__ __forceinline__ void mma16816(float* d, uint32_t a0, uint32_t a1, uint32_t a2, uint32_t a3,
                                         uint32_t b0, uint32_t b1) {
    asm volatile("mma.sync.aligned.m16n8k16.row.col.f32.f16.f16.f32 "
        "{%0,%1,%2,%3}, {%4,%5,%6,%7}, {%8,%9}, {%0,%1,%2,%3};"
        : "+f"(d[0]), "+f"(d[1]), "+f"(d[2]), "+f"(d[3])
        : "r"(a0), "r"(a1), "r"(a2), "r"(a3), "r"(b0), "r"(b1));
}
#define SWZ(x) ((uint32_t)(x) ^ ((((uint32_t)(x)) >> 3) & 0x70))

// ---------------- device scratch ----------------
__device__ __half g_Xh  [(size_t)TOK * DD];
__device__ __half g_W1ah[(size_t)NE * DD * FF];      // [E][D][F]
__device__ __half g_W1bh[(size_t)NE * DD * FF];
__device__ __half g_W2h [(size_t)NE * FF * DD];      // [E][F][D]
__device__ __half g_H   [(size_t)2 * TOK * FF];
__device__ __half g_Yh  [(size_t)2 * TOK * DD];      // expert output, fp16
__device__ int    g_cnt [NE];
__device__ int    g_off [NE];
__device__ int    g_tlist[NE * TOK];
__device__ int    g_loc [2 * TOK];
__device__ int    g_exp [2 * TOK];
__device__ float  g_gw  [2 * TOK];

// ---------------- small kernels ----------------
__global__ void k_init_cnt() { if (threadIdx.x < NE) g_cnt[threadIdx.x] = 0; }

// W1a/W1b conversion, 2 float4 per thread (blockIdx.y: 0=W1a, 1=W1b)
__global__ void k_cvt_ab(const float* __restrict__ a, const float* __restrict__ b) {
    const float* src = blockIdx.y ? b : a;
    __half* dst = blockIdx.y ? g_W1bh : g_W1ah;
    size_t i = 2 * ((size_t)blockIdx.x * blockDim.x + threadIdx.x);
    float4 v0 = ((const float4*)src)[i];
    float4 v1 = ((const float4*)src)[i + 1];
    __half2* d2 = (__half2*)dst;
    d2[2 * i]     = __floats2half2_rn(v0.x, v0.y);
    d2[2 * i + 1] = __floats2half2_rn(v0.z, v0.w);
    d2[2 * i + 2] = __floats2half2_rn(v1.x, v1.y);
    d2[2 * i + 3] = __floats2half2_rn(v1.z, v1.w);
}

// W2 conversion, 2 float4 per thread
__global__ void k_cvt_w2(const float* __restrict__ src) {
    size_t i = 2 * ((size_t)blockIdx.x * blockDim.x + threadIdx.x);
    float4 v0 = ((const float4*)src)[i];
    float4 v1 = ((const float4*)src)[i + 1];
    __half2* d2 = (__half2*)g_W2h;
    d2[2 * i]     = __floats2half2_rn(v0.x, v0.y);
    d2[2 * i + 1] = __floats2half2_rn(v0.z, v0.w);
    d2[2 * i + 2] = __floats2half2_rn(v1.x, v1.y);
    d2[2 * i + 3] = __floats2half2_rn(v1.z, v1.w);
}

// RMSNorm + gating (coalesced) + top-2 + scatter. One block per token, 256 threads.
__global__ void k_rms_gate(const float* __restrict__ x,
                           const float* __restrict__ lnw,
                           const float* __restrict__ Wg,
                           const float* __restrict__ bg) {
    int t = blockIdx.x;
    int tid = threadIdx.x, warp = tid >> 5, lane = tid & 31;

    __shared__ float red[8];
    __shared__ float sscale;
    __shared__ __align__(16) float sxn[DD];
    __shared__ float pe[8][8];

    float4 v = ((const float4*)(x + (size_t)t * DD))[tid];
    float ss = v.x * v.x + v.y * v.y + v.z * v.z + v.w * v.w;
#pragma unroll
    for (int o = 16; o; o >>= 1) ss += __shfl_xor_sync(0xffffffffu, ss, o);
    if (lane == 0) red[warp] = ss;
    __syncthreads();
    if (tid == 0) {
        float tot = 0.f;
#pragma unroll
        for (int w = 0; w < 8; w++) tot += red[w];
        sscale = rsqrtf(tot * (1.0f / (float)DD) + 1.1920928955078125e-7f);
    }
    __syncthreads();
    float s = sscale;

    float4 lw = ((const float4*)lnw)[tid];
    float4 xn;
    xn.x = v.x * s * lw.x; xn.y = v.y * s * lw.y;
    xn.z = v.z * s * lw.z; xn.w = v.w * s * lw.w;

    __half2* xh = (__half2*)(g_Xh + (size_t)t * DD);
    xh[2 * tid]     = __floats2half2_rn(xn.x, xn.y);
    xh[2 * tid + 1] = __floats2half2_rn(xn.z, xn.w);

    ((float4*)sxn)[tid] = xn;
    __syncthreads();

    {
        int dbase = tid >> 3;
        float acc = 0.f;
#pragma unroll
        for (int i = 0; i < 32; i++)
            acc += __ldg(&Wg[tid + 256 * i]) * sxn[dbase + 32 * i];
        acc += __shfl_xor_sync(0xffffffffu, acc, 8);
        acc += __shfl_xor_sync(0xffffffffu, acc, 16);
        if (lane < 8) pe[warp][lane] = acc;
    }
    __syncthreads();

    if (tid == 0) {
        float lg[8];
#pragma unroll
        for (int e = 0; e < 8; e++) {
            float acc = bg[e];
#pragma unroll
            for (int w = 0; w < 8; w++) acc += pe[w][e];
            lg[e] = acc;
        }
        int i1 = 0;
#pragma unroll
        for (int e = 1; e < 8; e++) if (lg[e] > lg[i1]) i1 = e;
        int i2 = -1;
#pragma unroll
        for (int e = 0; e < 8; e++) {
            if (e == i1) continue;
            if (i2 < 0 || lg[e] > lg[i2]) i2 = e;
        }
        float z  = expf(lg[i2] - lg[i1]);
        float w1 = 1.0f / (1.0f + z);
        float w2 = 1.0f - w1;

        int p1 = atomicAdd(&g_cnt[i1], 1);
        g_tlist[i1 * TOK + p1] = t;
        g_loc[2 * t] = p1; g_exp[2 * t] = i1; g_gw[2 * t] = w1;

        int p2 = atomicAdd(&g_cnt[i2], 1);
        g_tlist[i2 * TOK + p2] = t;
        g_loc[2 * t + 1] = p2; g_exp[2 * t + 1] = i2; g_gw[2 * t + 1] = w2;
    }
}

__global__ void k_prefix() {
    int acc = 0;
#pragma unroll
    for (int e = 0; e < NE; e++) { g_off[e] = acc; acc += g_cnt[e]; }
}

// ================= GEMM 1: H = silu(X@W1a+b1a)*(X@W1b+b1b)  (R12 loaders, .cg) =================
// CTA 128x64 (both weights), BK=64, 3-stage cp.async. stage 32KB; x3 = 96KB; occ 2.
#define G1_STAGE 32768
#define G1_SMEM  (G1_STAGE * 3)
__global__ __launch_bounds__(256, 2)
void k_gemm1(const float* __restrict__ b1a, const float* __restrict__ b1b) {
    extern __shared__ __align__(16) char smem[];
    int e   = blockIdx.z;
    int cnt = g_cnt[e];
    int m0  = blockIdx.y * 128;
    if (m0 >= cnt) return;
    int n0  = blockIdx.x * 64;

    uint32_t sb = smem_u32(smem);
    int tid = threadIdx.x, warp = tid >> 5, lane = tid & 31;
    int wm = warp >> 1, wn = warp & 1;   // 4x2 warp grid; warp tile 32 x 32 (per matrix)

    int lrow = tid >> 3;
    int lc   = tid & 7;
    int tok[4];
    bool ap[4];
#pragma unroll
    for (int i = 0; i < 4; i++) {
        int r = lrow + 32 * i;
        ap[i]  = (m0 + r < cnt);
        tok[i] = ap[i] ? g_tlist[e * TOK + m0 + r] : 0;
    }
    const __half* Wa = g_W1ah + (size_t)e * DD * FF + n0 + lc * 8;
    const __half* Wb = g_W1bh + (size_t)e * DD * FF + n0 + lc * 8;

    float accA[2][4][4], accB[2][4][4];
#pragma unroll
    for (int i = 0; i < 2; i++)
#pragma unroll
        for (int j = 0; j < 4; j++)
#pragma unroll
            for (int q = 0; q < 4; q++) { accA[i][j][q] = 0.f; accB[i][j][q] = 0.f; }

    auto load_stage = [&](int s, int k0) {
        uint32_t base = sb + s * G1_STAGE;
#pragma unroll
        for (int i = 0; i < 4; i++) {
            int r = lrow + 32 * i;
            cp16p(base + SWZ(r * 128 + lc * 16), g_Xh + (size_t)tok[i] * DD + k0 + lc * 8, ap[i]);
        }
#pragma unroll
        for (int i = 0; i < 2; i++) {
            int r = lrow + 32 * i;
            uint32_t o = SWZ(r * 128 + lc * 16);
            cp16(base + 16384 + o, Wa + (size_t)(k0 + r) * FF);
            cp16(base + 24576 + o, Wb + (size_t)(k0 + r) * FF);
        }
    };

    const int ITERS = DD / 64;   // 16
    load_stage(0, 0);  CP_COMMIT();
    load_stage(1, 64); CP_COMMIT();

    int l16 = lane & 15, lh = lane >> 4;
    for (int it = 0; it < ITERS; ++it) {
        CP_WAIT(1);
        __syncthreads();
        if (it + 2 < ITERS) load_stage((it + 2) % 3, (it + 2) * 64);
        CP_COMMIT();

        uint32_t Ab  = sb + (it % 3) * G1_STAGE;
        uint32_t Bab = Ab + 16384;
        uint32_t Bbb = Ab + 24576;
#pragma unroll
        for (int kk = 0; kk < 4; kk++) {
            uint32_t a[2][4];
#pragma unroll
            for (int i = 0; i < 2; i++)
                ldsm4(a[i][0], a[i][1], a[i][2], a[i][3],
                      Ab + SWZ((wm * 32 + i * 16 + l16) * 128 + kk * 32 + lh * 16));
#pragma unroll
            for (int jb = 0; jb < 2; jb++) {
                uint32_t boff = SWZ((kk * 16 + l16) * 128 + wn * 64 + jb * 32 + lh * 16);
                uint32_t b0, b1, b2, b3;
                ldsm4t(b0, b1, b2, b3, Bab + boff);
#pragma unroll
                for (int i = 0; i < 2; i++) {
                    mma16816(accA[i][jb * 2],     a[i][0], a[i][1], a[i][2], a[i][3], b0, b1);
                    mma16816(accA[i][jb * 2 + 1], a[i][0], a[i][1], a[i][2], a[i][3], b2, b3);
                }
                ldsm4t(b0, b1, b2, b3, Bbb + boff);
#pragma unroll
                for (int i = 0; i < 2; i++) {
                    mma16816(accB[i][jb * 2],     a[i][0], a[i][1], a[i][2], a[i][3], b0, b1);
                    mma16816(accB[i][jb * 2 + 1], a[i][0], a[i][1], a[i][2], a[i][3], b2, b3);
                }
            }
        }
    }

    int off_e = g_off[e];
    int r_lo = lane >> 2, cp2 = (lane & 3) * 2;
#pragma unroll
    for (int i = 0; i < 2; i++) {
#pragma unroll
        for (int rr = 0; rr < 2; rr++) {
            int m = m0 + wm * 32 + i * 16 + rr * 8 + r_lo;
            if (m >= cnt) continue;
            __half* Hrow = g_H + (size_t)(off_e + m) * FF;
#pragma unroll
            for (int j = 0; j < 4; j++) {
                int nc = n0 + wn * 32 + j * 8 + cp2;
                float a0 = accA[i][j][rr * 2]     + __ldg(&b1a[(size_t)e * FF + nc]);
                float a1 = accA[i][j][rr * 2 + 1] + __ldg(&b1a[(size_t)e * FF + nc + 1]);
                float v0 = accB[i][j][rr * 2]     + __ldg(&b1b[(size_t)e * FF + nc]);
                float v1 = accB[i][j][rr * 2 + 1] + __ldg(&b1b[(size_t)e * FF + nc + 1]);
                float h0 = a0 / (1.0f + __expf(-a0)) * v0;
                float h1 = a1 / (1.0f + __expf(-a1)) * v1;
                *(__half2*)(Hrow + nc) = __floats2half2_rn(h0, h1);
            }
        }
    }
}

// ================= GEMM 2: Y = H @ W2 + b2 (fp16 Y)  (R12 loaders, .cg) =================
// CTA 128x128, BK=64, B as two 64-col panels. stage 32KB; x3 = 96KB; occ 2.
#define G2_STAGE 32768
#define G2_SMEM  (G2_STAGE * 3)
__global__ __launch_bounds__(256, 2)
void k_gemm2(const float* __restrict__ b2) {
    extern __shared__ __align__(16) char smem[];
    int e   = blockIdx.z;
    int cnt = g_cnt[e];
    int m0  = blockIdx.y * 128;
    if (m0 >= cnt) return;
    int n0  = blockIdx.x * 128;

    uint32_t sb = smem_u32(smem);
    int tid = threadIdx.x, warp = tid >> 5, lane = tid & 31;
    int wm = warp >> 1, wn = warp & 1;

    int off_e = g_off[e];
    int lrow = tid >> 3;
    int lc   = tid & 7;
    bool ap[4];
    const __half* Arow[4];
#pragma unroll
    for (int i = 0; i < 4; i++) {
        int r = lrow + 32 * i;
        ap[i]   = (m0 + r < cnt);
        Arow[i] = g_H + (size_t)(off_e + (ap[i] ? m0 + r : 0)) * FF;
    }
    const __half* WB = g_W2h + (size_t)e * FF * DD + n0 + lc * 8;

    float acc[2][8][4];
#pragma unroll
    for (int i = 0; i < 2; i++)
#pragma unroll
        for (int j = 0; j < 8; j++)
#pragma unroll
            for (int q = 0; q < 4; q++) acc[i][j][q] = 0.f;

    auto load_stage = [&](int s, int k0) {
        uint32_t base = sb + s * G2_STAGE;
#pragma unroll
        for (int i = 0; i < 4; i++) {
            int r = lrow + 32 * i;
            cp16p(base + SWZ(r * 128 + lc * 16), Arow[i] + k0 + lc * 8, ap[i]);
        }
#pragma unroll
        for (int p = 0; p < 2; p++)
#pragma unroll
            for (int i = 0; i < 2; i++) {
                int r = lrow + 32 * i;
                cp16(base + 16384 + p * 8192 + SWZ(r * 128 + lc * 16),
                     WB + (size_t)(k0 + r) * DD + p * 64);
            }
    };

    const int ITERS = FF / 64;   // 64
    load_stage(0, 0);  CP_COMMIT();
    load_stage(1, 64); CP_COMMIT();

    int l16 = lane & 15, lh = lane >> 4;
    for (int it = 0; it < ITERS; ++it) {
        CP_WAIT(1);
        __syncthreads();
        if (it + 2 < ITERS) load_stage((it + 2) % 3, (it + 2) * 64);
        CP_COMMIT();

        uint32_t Ab = sb + (it % 3) * G2_STAGE;
        uint32_t Bb = Ab + 16384 + wn * 8192;   // this warp's 64-col panel
#pragma unroll
        for (int kk = 0; kk < 4; kk++) {
            uint32_t a[2][4];
#pragma unroll
            for (int i = 0; i < 2; i++)
                ldsm4(a[i][0], a[i][1], a[i][2], a[i][3],
                      Ab + SWZ((wm * 32 + i * 16 + l16) * 128 + kk * 32 + lh * 16));
#pragma unroll
            for (int jb = 0; jb < 4; jb++) {
                uint32_t b0, b1, b2, b3;
                ldsm4t(b0, b1, b2, b3, Bb + SWZ((kk * 16 + l16) * 128 + jb * 32 + lh * 16));
#pragma unroll
                for (int i = 0; i < 2; i++) {
                    mma16816(acc[i][jb * 2],     a[i][0], a[i][1], a[i][2], a[i][3], b0, b1);
                    mma16816(acc[i][jb * 2 + 1], a[i][0], a[i][1], a[i][2], a[i][3], b2, b3);
                }
            }
        }
    }

    int r_lo = lane >> 2, cp2 = (lane & 3) * 2;
#pragma unroll
    for (int i = 0; i < 2; i++) {
#pragma unroll
        for (int rr = 0; rr < 2; rr++) {
            int m = m0 + wm * 32 + i * 16 + rr * 8 + r_lo;
            if (m >= cnt) continue;
            __half* Yrow = g_Yh + (size_t)(off_e + m) * DD;
#pragma unroll
            for (int j = 0; j < 8; j++) {
                int nc = n0 + wn * 64 + j * 8 + cp2;
                float y0 = acc[i][j][rr * 2]     + __ldg(&b2[(size_t)e * DD + nc]);
                float y1 = acc[i][j][rr * 2 + 1] + __ldg(&b2[(size_t)e * DD + nc + 1]);
                *(__half2*)(Yrow + nc) = __floats2half2_rn(y0, y1);
            }
        }
    }
}

// ---------------- combine (fp16 Y inputs) ----------------
__global__ void k_combine(float* __restrict__ out) {
    int t = blockIdx.x;
    int e0 = g_exp[2 * t], e1 = g_exp[2 * t + 1];
    size_t r0 = (size_t)(g_off[e0] + g_loc[2 * t]);
    size_t r1 = (size_t)(g_off[e1] + g_loc[2 * t + 1]);
    float w0 = g_gw[2 * t], w1 = g_gw[2 * t + 1];

    const uint2* y0 = (const uint2*)(g_Yh + r0 * DD);
    const uint2* y1 = (const uint2*)(g_Yh + r1 * DD);
    uint2 pa = y0[threadIdx.x];
    uint2 pb = y1[threadIdx.x];
    __half2 a01 = *(__half2*)&pa.x, a23 = *(__half2*)&pa.y;
    __half2 b01 = *(__half2*)&pb.x, b23 = *(__half2*)&pb.y;
    float2 fa01 = __half22float2(a01), fa23 = __half22float2(a23);
    float2 fb01 = __half22float2(b01), fb23 = __half22float2(b23);
    float4 o;
    o.x = w0 * fa01.x + w1 * fb01.x;
    o.y = w0 * fa01.y + w1 * fb01.y;
    o.z = w0 * fa23.x + w1 * fb23.x;
    o.w = w0 * fa23.y + w1 * fb23.y;
    ((float4*)(out + (size_t)t * DD))[threadIdx.x] = o;
}

// ---------------- launch ----------------
extern "C" void kernel_launch(void* const* d_in, const int* in_sizes, int n_in,
                              void* d_out, int out_size) {
    const float* x   = (const float*)d_in[0];
    const float* lnw = (const float*)d_in[1];
    const float* Wg  = (const float*)d_in[2];
    const float* bg  = (const float*)d_in[3];
    const float* W1a = (const float*)d_in[4];
    const float* b1a = (const float*)d_in[5];
    const float* W1b = (const float*)d_in[6];
    const float* b1b = (const float*)d_in[7];
    const float* W2  = (const float*)d_in[8];
    const float* b2  = (const float*)d_in[9];
    float* out = (float*)d_out;

    static int inited = 0;
    static cudaStream_t s1;
    static cudaEvent_t evFork, evAb, evW2;
    if (!inited) {
        cudaFuncSetAttribute(k_gemm1, cudaFuncAttributeMaxDynamicSharedMemorySize, G1_SMEM);
        cudaFuncSetAttribute(k_gemm2, cudaFuncAttributeMaxDynamicSharedMemorySize, G2_SMEM);
        cudaStreamCreateWithFlags(&s1, cudaStreamNonBlocking);
        cudaEventCreateWithFlags(&evFork, cudaEventDisableTiming);
        cudaEventCreateWithFlags(&evAb, cudaEventDisableTiming);
        cudaEventCreateWithFlags(&evW2, cudaEventDisableTiming);
        inited = 1;
    }

    k_init_cnt<<<1, 32>>>();

    // fork conversion stream off the capture (default) stream
    cudaEventRecord(evFork, 0);
    cudaStreamWaitEvent(s1, evFork, 0);

    const int n8 = NE * DD * FF / 8;   // 2-float4 units per weight tensor
    k_cvt_ab<<<dim3(n8 / 256, 2), 256, 0, s1>>>(W1a, W1b);
    cudaEventRecord(evAb, s1);
    k_cvt_w2<<<n8 / 256, 256, 0, s1>>>(W2);
    cudaEventRecord(evW2, s1);

    // routing on the main stream, concurrent with conversions
    k_rms_gate<<<TOK, 256>>>(x, lnw, Wg, bg);
    k_prefix<<<1, 1>>>();

    cudaStreamWaitEvent(0, evAb, 0);
    k_gemm1<<<dim3(FF / 64, TOK / 128, NE), 256, G1_SMEM>>>(b1a, b1b);

    cudaStreamWaitEvent(0, evW2, 0);
    k_gemm2<<<dim3(DD / 128, TOK / 128, NE), 256, G2_SMEM>>>(b2);

    k_combine<<<TOK, 256>>>(out);
}